// round 9
// baseline (speedup 1.0000x reference)
#include <cuda_runtime.h>
#include <stdint.h>

#define THREADS 128
#define ROWS    32       // rows per block
#define PCOUNT  64       // predicates
#define PAD     33       // conflict-free row stride in shared (ROWS+1)
#define C_MAX   128
#define NSPLIT  4        // clause quarters, one per warp
#define EROWS   128      // E-table: exp(+g_p) at row p, exp(-g_p) at row p+64

// Clause tables, all offsets pre-scaled to BYTES (kills IMADs in main loop):
// g_t1[c] = {e0B, e1B, e2B, a0B}            e = (p + (sb?0:64))*PAD*4, a = p*PAD*4
// g_t2[c] = {a1B | a2B<<16, w0, w1, w2}     w pre-signed: sb ? +w : -w
__device__ uint4  g_t1[C_MAX];
__device__ uint4  g_t2[C_MAX];

__device__ __forceinline__ float frcp(float x){ float y; asm("rcp.approx.f32 %0, %1;" : "=f"(y) : "f"(x)); return y; }
__device__ __forceinline__ float fex2(float x){ float y; asm("ex2.approx.f32 %0, %1;" : "=f"(y) : "f"(x)); return y; }

// literal_idx may physically be int32 (JAX x64-disabled) or int64; detect:
// int64 view of int32 data fuses two random indices -> out of [0,64) w.h.p.
__global__ void prep_kernel(const float* __restrict__ cw,
                            const void* __restrict__ litraw,
                            const int* __restrict__ sgn, int C)
{
    __shared__ int sh_is64;
    if (threadIdx.x == 0){
        const long long* v64 = (const long long*)litraw;
        int n = (C * 3) / 2;              // stays within int32-buffer bounds
        int ok = 1;
        for (int k = 0; k < n; k++){
            long long v = v64[k];
            if (v < 0 || v >= PCOUNT){ ok = 0; break; }
        }
        sh_is64 = ok;
    }
    __syncthreads();
    const int is64 = sh_is64;

    int c = blockIdx.x * blockDim.x + threadIdx.x;
    if (c >= C) return;
    float w = fminf(fmaxf(cw[c], 0.0f), 500.0f);     // clamp(0, 500)
    unsigned e[3], a[3]; float s[3];
    #pragma unroll
    for (int l = 0; l < 3; l++){
        int p = is64 ? (int)((const long long*)litraw)[c*3 + l]
                     :       ((const int*)litraw)[c*3 + l];
        int sb = sgn[c*3 + l];            // 1 -> +g half (+w), 0 -> -g half (-w)
        e[l] = (unsigned)((p + (sb ? 0 : PCOUNT)) * PAD * 4);   // byte offset
        a[l] = (unsigned)(p * PAD * 4);                         // byte offset
        s[l] = sb ? w : -w;
    }
    g_t1[c] = make_uint4(e[0], e[1], e[2], a[0]);
    g_t2[c] = make_uint4(a[1] | (a[2] << 16),
                         __float_as_uint(s[0]), __float_as_uint(s[1]), __float_as_uint(s[2]));
}

__global__ void __launch_bounds__(THREADS, 4)      // 4 blocks/SM target -> 128 regs/thread budget
main_kernel(const float* __restrict__ ga, float* __restrict__ out, int B)
{
    extern __shared__ char shb[];
    float* sh = (float*)shb;
    float* __restrict__ E = sh;                                // EROWS*PAD = 4224 f
    float* __restrict__ A = sh + EROWS*PAD;                    // NSPLIT * 64*33 = 8448 f
    uint4*  T1 = (uint4*)(sh + EROWS*PAD + NSPLIT*PCOUNT*PAD);
    uint4*  T2 = T1 + C_MAX;

    const int tid  = threadIdx.x;
    const int lane = tid & 31;
    const int wrp  = tid >> 5;
    const long long rowbase = (long long)blockIdx.x * ROWS;
    long long rem = (long long)B - rowbase;
    const int nrows = rem < ROWS ? (int)rem : ROWS;
    const size_t base = (size_t)rowbase * PCOUNT;

    if (tid < C_MAX){ T1[tid] = g_t1[tid]; T2[tid] = g_t2[tid]; }

    // zero all 4 accumulator copies (vectorized)
    float4* A4 = (float4*)A;
    #pragma unroll
    for (int i = tid; i < NSPLIT*PCOUNT*PAD/4; i += THREADS)
        A4[i] = make_float4(0.f, 0.f, 0.f, 0.f);

    // Phase A: coalesced 32x64 tile load; build exp table (exp(+g), rcp(exp)).
    const float4* ga4 = (const float4*)(ga + base);
    const float L2E = 1.4426950408889634f;
    #pragma unroll
    for (int i = tid; i < ROWS*PCOUNT/4; i += THREADS){
        int o = i * 4, row = o >> 6, p = o & (PCOUNT-1);
        if (row < nrows){
            float4 g = ga4[i];
            float t;
            t = fex2(g.x*L2E); E[(p  )*PAD+row] = t; E[(p+PCOUNT  )*PAD+row] = frcp(t);
            t = fex2(g.y*L2E); E[(p+1)*PAD+row] = t; E[(p+PCOUNT+1)*PAD+row] = frcp(t);
            t = fex2(g.z*L2E); E[(p+2)*PAD+row] = t; E[(p+PCOUNT+2)*PAD+row] = frcp(t);
            t = fex2(g.w*L2E); E[(p+3)*PAD+row] = t; E[(p+PCOUNT+3)*PAD+row] = frcp(t);
        }
    }
    __syncthreads();

    // Phase B: warp w owns clause quarter [32w, 32w+32) and private acc copy.
    // Byte-offset addressing: all gathers/RMWs are base + preloaded byte offset
    // (IADD only). Unroll 16 + the 128-reg budget lets ptxas hoist E-gathers and
    // table loads of many clauses above the serial may-alias acc-RMW tail.
    {
        const char* __restrict__ Eb = (const char*)E + (size_t)lane * 4;
        char* __restrict__ Ab = (char*)(A + wrp * (PCOUNT*PAD)) + (size_t)lane * 4;
        const int c0 = wrp * (C_MAX/NSPLIT);
        #pragma unroll 16
        for (int c = c0; c < c0 + C_MAX/NSPLIT; c++){
            uint4 t1 = T1[c], t2 = T2[c];
            unsigned a0 = t1.w, a1 = t2.x & 0xFFFF, a2 = t2.x >> 16;
            float x0 = *(const float*)(Eb + t1.x);
            float x1 = *(const float*)(Eb + t1.y);
            float x2 = *(const float*)(Eb + t1.z);
            float r  = frcp(x0 + x1 + x2);               // 1/sum(exp)
            float* p0 = (float*)(Ab + a0);
            float* p1 = (float*)(Ab + a1);
            float* p2 = (float*)(Ab + a2);
            *p0 = fmaf(__uint_as_float(t2.y), x0*r, *p0);
            *p1 = fmaf(__uint_as_float(t2.z), x1*r, *p1);
            *p2 = fmaf(__uint_as_float(t2.w), x2*r, *p2);
        }
    }
    __syncthreads();

    // Reduce the 4 per-warp accumulator copies into copy 0 (vectorized).
    {
        const int n4 = PCOUNT*PAD/4;   // 528
        #pragma unroll
        for (int i = tid; i < n4; i += THREADS){
            float4 a = A4[i], b = A4[i + n4], c = A4[i + 2*n4], d = A4[i + 3*n4];
            a.x += b.x + c.x + d.x;
            a.y += b.y + c.y + d.y;
            a.z += b.z + c.z + d.z;
            a.w += b.w + c.w + d.w;
            A4[i] = a;
        }
    }
    __syncthreads();

    // Phase C: coalesced store of the 32x64 output tile (column reads are
    // conflict-free thanks to PAD=33).
    float4* out4 = (float4*)(out + base);
    #pragma unroll
    for (int i = tid; i < ROWS*PCOUNT/4; i += THREADS){
        int o = i*4, row = o >> 6, p = o & (PCOUNT-1);
        if (row < nrows){
            float4 v;
            v.x = A[(p  )*PAD + row];
            v.y = A[(p+1)*PAD + row];
            v.z = A[(p+2)*PAD + row];
            v.w = A[(p+3)*PAD + row];
            out4[i] = v;
        }
    }
}

extern "C" void kernel_launch(void* const* d_in, const int* in_sizes, int n_in,
                              void* d_out, int out_size)
{
    const float* ga  = (const float*)d_in[0];      // ground_atoms [B,64] f32
    const float* cw  = (const float*)d_in[1];      // clause_weights [C] f32
    const void*  lit = d_in[2];                    // literal_idx [C,3] i32-or-i64
    const int*   sgn = (const int*)d_in[3];        // sign_bits [C,3] i32
    float* out = (float*)d_out;

    int C = in_sizes[1];
    int B = in_sizes[0] / PCOUNT;
    int nblocks = (B + ROWS - 1) / ROWS;
    size_t smem = (size_t)(EROWS*PAD + NSPLIT*PCOUNT*PAD) * sizeof(float)
                + 2 * C_MAX * sizeof(uint4);       // ~54.7 KB -> 4 blocks/SM

    cudaFuncSetAttribute(main_kernel, cudaFuncAttributeMaxDynamicSharedMemorySize, (int)smem);
    prep_kernel<<<1, THREADS>>>(cw, lit, sgn, C);
    main_kernel<<<nblocks, THREADS, smem>>>(ga, out, B);
}

// round 10
// speedup vs baseline: 1.6404x; 1.6404x over previous
#include <cuda_runtime.h>
#include <cuda_fp16.h>
#include <stdint.h>

#define THREADS 128
#define ROWS    32       // rows per block
#define PCOUNT  64       // predicates
#define PAD     33       // conflict-free row stride (ROWS+1)
#define C_MAX   128
#define NSPLIT  4        // clause quarters, one per warp
#define EROWS   128      // E-table: exp(+g_p) at row p, exp(-g_p) at row p+64
#define ENEG    (PCOUNT*PAD)   // 2112: element offsets >= this are negative literals

// One descriptor per clause (16B): {e0|e1<<16, e2|a0<<16, a1|a2<<16, w_bits}
// e = (p + (sb?0:64))*PAD  (element offset into half E-table)
// a = p*PAD                (element offset into float acc copy)
// per-literal sign recovered from e >= ENEG (arithmetic, branch-free)
__device__ uint4 g_tab[C_MAX];

__device__ __forceinline__ float frcp(float x){ float y; asm("rcp.approx.f32 %0, %1;" : "=f"(y) : "f"(x)); return y; }
__device__ __forceinline__ float fex2(float x){ float y; asm("ex2.approx.f32 %0, %1;" : "=f"(y) : "f"(x)); return y; }

// literal_idx may physically be int32 (JAX x64-disabled) or int64; detect:
// int64 view of int32 data fuses two random indices -> out of [0,64) w.h.p.
__global__ void prep_kernel(const float* __restrict__ cw,
                            const void* __restrict__ litraw,
                            const int* __restrict__ sgn, int C)
{
    __shared__ int sh_is64;
    if (threadIdx.x == 0){
        const long long* v64 = (const long long*)litraw;
        int n = (C * 3) / 2;              // stays within int32-buffer bounds
        int ok = 1;
        for (int k = 0; k < n; k++){
            long long v = v64[k];
            if (v < 0 || v >= PCOUNT){ ok = 0; break; }
        }
        sh_is64 = ok;
    }
    __syncthreads();
    const int is64 = sh_is64;

    int c = blockIdx.x * blockDim.x + threadIdx.x;
    if (c >= C) return;
    float w = fminf(fmaxf(cw[c], 0.0f), 500.0f);     // clamp(0, 500); w >= 0
    unsigned e[3], a[3];
    #pragma unroll
    for (int l = 0; l < 3; l++){
        int p = is64 ? (int)((const long long*)litraw)[c*3 + l]
                     :       ((const int*)litraw)[c*3 + l];
        int sb = sgn[c*3 + l];            // 1 -> +g half (+w), 0 -> -g half (-w)
        e[l] = (unsigned)((p + (sb ? 0 : PCOUNT)) * PAD);
        a[l] = (unsigned)(p * PAD);
    }
    g_tab[c] = make_uint4(e[0] | (e[1] << 16), e[2] | (a[0] << 16),
                          a[1] | (a[2] << 16), __float_as_uint(w));
}

__global__ void __launch_bounds__(THREADS)
main_kernel(const float* __restrict__ ga, float* __restrict__ out, int B)
{
    extern __shared__ char shb[];
    // layout: acc (33792B) | tab (2048B) | E half (8448B)  = 44288B -> 5 blocks/SM
    float*  __restrict__ A  = (float*)shb;
    uint4*  TB = (uint4*)(shb + NSPLIT*PCOUNT*PAD*4);
    __half* __restrict__ Eh = (__half*)(TB + C_MAX);

    const int tid  = threadIdx.x;
    const int lane = tid & 31;
    const int wrp  = tid >> 5;
    const long long rowbase = (long long)blockIdx.x * ROWS;
    long long rem = (long long)B - rowbase;
    const int nrows = rem < ROWS ? (int)rem : ROWS;
    const size_t base = (size_t)rowbase * PCOUNT;

    if (tid < C_MAX) TB[tid] = g_tab[tid];

    // zero the 4 accumulator copies (vectorized)
    float4* A4 = (float4*)A;
    #pragma unroll
    for (int i = tid; i < NSPLIT*PCOUNT*PAD/4; i += THREADS)
        A4[i] = make_float4(0.f, 0.f, 0.f, 0.f);

    // Phase A: coalesced 32x64 tile load; build fp16 exp table (exp(+g), rcp).
    const float4* ga4 = (const float4*)(ga + base);
    const float L2E = 1.4426950408889634f;
    #pragma unroll
    for (int i = tid; i < ROWS*PCOUNT/4; i += THREADS){
        int o = i * 4, row = o >> 6, p = o & (PCOUNT-1);
        if (row < nrows){
            float4 g = ga4[i];
            float t;
            t = fex2(g.x*L2E); Eh[(p  )*PAD+row] = __float2half(t); Eh[(p+PCOUNT  )*PAD+row] = __float2half(frcp(t));
            t = fex2(g.y*L2E); Eh[(p+1)*PAD+row] = __float2half(t); Eh[(p+PCOUNT+1)*PAD+row] = __float2half(frcp(t));
            t = fex2(g.z*L2E); Eh[(p+2)*PAD+row] = __float2half(t); Eh[(p+PCOUNT+2)*PAD+row] = __float2half(frcp(t));
            t = fex2(g.w*L2E); Eh[(p+3)*PAD+row] = __float2half(t); Eh[(p+PCOUNT+3)*PAD+row] = __float2half(frcp(t));
        }
    }
    __syncthreads();

    // Phase B: warp w owns clause quarter [32w, 32w+32) and private acc copy.
    // Identical structure to the 54.4us kernel: typed float*, element offsets,
    // unroll 8. Gathers (LDS.U16 lane-consecutive) and acc RMWs conflict-free.
    {
        float* __restrict__ Aw = A + wrp * (PCOUNT*PAD);
        const int c0 = wrp * (C_MAX/NSPLIT);
        #pragma unroll 8
        for (int c = c0; c < c0 + C_MAX/NSPLIT; c++){
            uint4 t = TB[c];
            int e0 = (int)(t.x & 0xFFFF), e1 = (int)(t.x >> 16);
            int e2 = (int)(t.y & 0xFFFF), a0 = (int)(t.y >> 16);
            int a1 = (int)(t.z & 0xFFFF), a2 = (int)(t.z >> 16);
            // sign via which E-half the offset points at (branch-free)
            float w0 = __uint_as_float(t.w | (((unsigned)(2111 - e0)) & 0x80000000u));
            float w1 = __uint_as_float(t.w | (((unsigned)(2111 - e1)) & 0x80000000u));
            float w2 = __uint_as_float(t.w | (((unsigned)(2111 - e2)) & 0x80000000u));
            float x0 = __half2float(Eh[e0 + lane]);
            float x1 = __half2float(Eh[e1 + lane]);
            float x2 = __half2float(Eh[e2 + lane]);
            float r  = frcp(x0 + x1 + x2);               // 1/sum(exp)
            Aw[a0 + lane] = fmaf(w0, x0*r, Aw[a0 + lane]);
            Aw[a1 + lane] = fmaf(w1, x1*r, Aw[a1 + lane]);
            Aw[a2 + lane] = fmaf(w2, x2*r, Aw[a2 + lane]);
        }
    }
    __syncthreads();

    // Reduce the 4 per-warp accumulator copies into copy 0 (vectorized).
    {
        const int n4 = PCOUNT*PAD/4;   // 528
        #pragma unroll
        for (int i = tid; i < n4; i += THREADS){
            float4 a = A4[i], b = A4[i + n4], c = A4[i + 2*n4], d = A4[i + 3*n4];
            a.x += b.x + c.x + d.x;
            a.y += b.y + c.y + d.y;
            a.z += b.z + c.z + d.z;
            a.w += b.w + c.w + d.w;
            A4[i] = a;
        }
    }
    __syncthreads();

    // Phase C: coalesced store of the 32x64 output tile (column reads are
    // conflict-free thanks to PAD=33).
    float4* out4 = (float4*)(out + base);
    #pragma unroll
    for (int i = tid; i < ROWS*PCOUNT/4; i += THREADS){
        int o = i*4, row = o >> 6, p = o & (PCOUNT-1);
        if (row < nrows){
            float4 v;
            v.x = A[(p  )*PAD + row];
            v.y = A[(p+1)*PAD + row];
            v.z = A[(p+2)*PAD + row];
            v.w = A[(p+3)*PAD + row];
            out4[i] = v;
        }
    }
}

extern "C" void kernel_launch(void* const* d_in, const int* in_sizes, int n_in,
                              void* d_out, int out_size)
{
    const float* ga  = (const float*)d_in[0];      // ground_atoms [B,64] f32
    const float* cw  = (const float*)d_in[1];      // clause_weights [C] f32
    const void*  lit = d_in[2];                    // literal_idx [C,3] i32-or-i64
    const int*   sgn = (const int*)d_in[3];        // sign_bits [C,3] i32
    float* out = (float*)d_out;

    int C = in_sizes[1];
    int B = in_sizes[0] / PCOUNT;
    int nblocks = (B + ROWS - 1) / ROWS;
    size_t smem = (size_t)NSPLIT*PCOUNT*PAD*4      // acc: 33792
                + C_MAX * sizeof(uint4)            // tab:  2048
                + (size_t)EROWS*PAD*2;             // E:    8448  => 44288 B -> 5 blocks/SM

    cudaFuncSetAttribute(main_kernel, cudaFuncAttributeMaxDynamicSharedMemorySize, (int)smem);
    prep_kernel<<<1, THREADS>>>(cw, lit, sgn, C);
    main_kernel<<<nblocks, THREADS, smem>>>(ga, out, B);
}